// round 1
// baseline (speedup 1.0000x reference)
#include <cuda_runtime.h>
#include <cstdint>
#include <cstddef>

// Problem dims (fixed by the dataset)
#define TOKENS 8192
#define HIDDEN 2048
#define INTER  5632

// ---------------------------------------------------------------------------
// Scratch (device globals; no allocation allowed in kernel_launch)
// ---------------------------------------------------------------------------
__device__ float g_wg[(size_t)HIDDEN * INTER];   // dequantized gate weight [H, I]
__device__ float g_wu[(size_t)HIDDEN * INTER];   // dequantized up weight   [H, I]
__device__ float g_wd[(size_t)INTER * HIDDEN];   // dequantized down weight [I, H]
__device__ float g_xr[(size_t)TOKENS * HIDDEN];  // x rounded to tf32
__device__ float g_g [(size_t)TOKENS * INTER];   // gate GEMM out, then h (in-place)
__device__ float g_u [(size_t)TOKENS * INTER];   // up GEMM out

// ---------------------------------------------------------------------------
// Helpers
// ---------------------------------------------------------------------------
__device__ __forceinline__ float to_tf32(float x) {
    float y;
    asm("cvt.rna.tf32.f32 %0, %1;" : "=f"(y) : "f"(x));
    return y;
}

__device__ __forceinline__ void cp_async16(void* smem_dst, const void* gsrc) {
    uint32_t s = (uint32_t)__cvta_generic_to_shared(smem_dst);
    asm volatile("cp.async.cg.shared.global [%0], [%1], 16;\n" :: "r"(s), "l"(gsrc));
}
__device__ __forceinline__ void cp_commit() {
    asm volatile("cp.async.commit_group;\n");
}

__device__ __forceinline__ void mma_tf32(float c[4], const float a[4], const float b[2]) {
    asm volatile(
        "mma.sync.aligned.m16n8k8.row.col.f32.tf32.tf32.f32 "
        "{%0,%1,%2,%3}, {%4,%5,%6,%7}, {%8,%9}, {%0,%1,%2,%3};\n"
        : "+f"(c[0]), "+f"(c[1]), "+f"(c[2]), "+f"(c[3])
        : "r"(__float_as_uint(a[0])), "r"(__float_as_uint(a[1])),
          "r"(__float_as_uint(a[2])), "r"(__float_as_uint(a[3])),
          "r"(__float_as_uint(b[0])), "r"(__float_as_uint(b[1])));
}

// ---------------------------------------------------------------------------
// GPTQ int4 dequant: w[k,o] = (q[k,o] - (z[g,o] + 1)) * s[g,o], group = k/128
// qweight: [in/8, out] int32 (8 k-nibbles per word, k%8 at shift 4*(k%8))
// qzeros : [in/128, out/8] int32 (8 o-nibbles per word, o%8 at shift 4*(o%8))
// scales : [in/128, out] fp32
// Output pre-rounded to tf32 so the GEMM's operand rounding is a no-op.
// ---------------------------------------------------------------------------
__global__ void dequant_kernel(const int* __restrict__ qw,
                               const int* __restrict__ qz,
                               const float* __restrict__ sc,
                               float* __restrict__ w,
                               int in_dim, int out) {
    int o = blockIdx.x * blockDim.x + threadIdx.x;
    int kp = blockIdx.y;               // packed row index: covers k = kp*8 .. kp*8+7
    if (o >= out) return;
    int grp = kp >> 4;                 // (kp*8)/128
    unsigned q = (unsigned)qw[(size_t)kp * out + o];
    unsigned zw = (unsigned)qz[(size_t)grp * (out >> 3) + (o >> 3)];
    int z = (int)((zw >> ((o & 7) * 4)) & 0xF) + 1;
    float s = sc[(size_t)grp * out + o];
#pragma unroll
    for (int j = 0; j < 8; j++) {
        int qv = (int)((q >> (4 * j)) & 0xF);
        w[(size_t)(kp * 8 + j) * out + o] = to_tf32((float)(qv - z) * s);
    }
}

// Round x to tf32 (vectorized)
__global__ void round_x_kernel(const float* __restrict__ x, float* __restrict__ y, int n4) {
    int i = blockIdx.x * blockDim.x + threadIdx.x;
    if (i >= n4) return;
    float4 v = reinterpret_cast<const float4*>(x)[i];
    v.x = to_tf32(v.x); v.y = to_tf32(v.y); v.z = to_tf32(v.z); v.w = to_tf32(v.w);
    reinterpret_cast<float4*>(y)[i] = v;
}

// h = tf32_round( silu(g) * u )   (h may alias g)
__global__ void silu_mul_kernel(const float* __restrict__ g, const float* __restrict__ u,
                                float* __restrict__ h, int n4) {
    int i = blockIdx.x * blockDim.x + threadIdx.x;
    if (i >= n4) return;
    float4 gv = reinterpret_cast<const float4*>(g)[i];
    float4 uv = reinterpret_cast<const float4*>(u)[i];
    float4 o;
    o.x = to_tf32(gv.x / (1.0f + __expf(-gv.x)) * uv.x);
    o.y = to_tf32(gv.y / (1.0f + __expf(-gv.y)) * uv.y);
    o.z = to_tf32(gv.z / (1.0f + __expf(-gv.z)) * uv.z);
    o.w = to_tf32(gv.w / (1.0f + __expf(-gv.w)) * uv.w);
    reinterpret_cast<float4*>(h)[i] = o;
}

// ---------------------------------------------------------------------------
// tf32 GEMM: C[M,N] = A[M,K] @ B[K,N]   (all fp32 storage, tf32 math)
// BM=128 BN=128 BK=32, 256 threads (8 warps as 2(M) x 4(N), warp tile 64x32)
// 2-stage cp.async pipeline. Requires M%128==0, N%128==0, K%32==0.
// ---------------------------------------------------------------------------
constexpr int BM = 128, BN = 128, BK = 32, STAGES = 2;
constexpr int AST = BK + 4;   // 36 floats/row (144B, 16B-aligned, conflict-free A frags)
constexpr int BST = BN + 4;   // 132 floats/row (528B, 16B-aligned, 2-way on B frags)
constexpr int SMEM_FLOATS = STAGES * (BM * AST + BK * BST);
constexpr size_t SMEM_BYTES = (size_t)SMEM_FLOATS * 4;

__global__ void __launch_bounds__(256)
gemm_tf32_kernel(const float* __restrict__ A, const float* __restrict__ B,
                 float* __restrict__ C, int M, int N, int K) {
    extern __shared__ float smem[];
    float* As = smem;
    float* Bs = smem + STAGES * BM * AST;

    const int tid  = threadIdx.x;
    const int lane = tid & 31;
    const int wid  = tid >> 5;
    const int warpM = wid & 1;     // 0..1
    const int warpN = wid >> 1;    // 0..3
    const int bm = blockIdx.y * BM;
    const int bn = blockIdx.x * BN;

    // Global->smem mapping: A tile 128x32 = 128 rows x 8 float4; B tile 32x128 = 32 x 32 float4
    const int af4 = tid & 7;       // float4 col in A row
    const int ar0 = tid >> 3;      // 0..31, rows ar0 + {0,32,64,96}
    const int bf4 = tid & 31;      // float4 col in B row
    const int br0 = tid >> 5;      // 0..7, rows br0 + {0,8,16,24}

    auto load_stage = [&](int st, int k0) {
        float* as = As + st * BM * AST;
        float* bs = Bs + st * BK * BST;
#pragma unroll
        for (int i = 0; i < 4; i++) {
            int r = ar0 + i * 32;
            cp_async16(as + r * AST + af4 * 4,
                       A + (size_t)(bm + r) * K + k0 + af4 * 4);
        }
#pragma unroll
        for (int i = 0; i < 4; i++) {
            int r = br0 + i * 8;
            cp_async16(bs + r * BST + bf4 * 4,
                       B + (size_t)(k0 + r) * N + bn + bf4 * 4);
        }
        cp_commit();
    };

    float acc[4][4][4];
#pragma unroll
    for (int mf = 0; mf < 4; mf++)
#pragma unroll
        for (int nf = 0; nf < 4; nf++)
#pragma unroll
            for (int i = 0; i < 4; i++) acc[mf][nf][i] = 0.0f;

    const int kTiles = K / BK;
    load_stage(0, 0);

    for (int kt = 0; kt < kTiles; ++kt) {
        const int cur = kt & 1;
        if (kt + 1 < kTiles) {
            load_stage(cur ^ 1, (kt + 1) * BK);
            asm volatile("cp.async.wait_group 1;\n");
        } else {
            asm volatile("cp.async.wait_group 0;\n");
        }
        __syncthreads();

        const float* as = As + cur * BM * AST + (warpM * 64) * AST;
        const float* bs = Bs + cur * BK * BST + warpN * 32;
#pragma unroll
        for (int kk = 0; kk < BK; kk += 8) {
            float a[4][4];
            float b[4][2];
#pragma unroll
            for (int mf = 0; mf < 4; mf++) {
                int r = mf * 16 + (lane >> 2);
                int kc = kk + (lane & 3);
                a[mf][0] = as[(size_t)r * AST + kc];
                a[mf][1] = as[(size_t)(r + 8) * AST + kc];
                a[mf][2] = as[(size_t)r * AST + kc + 4];
                a[mf][3] = as[(size_t)(r + 8) * AST + kc + 4];
            }
#pragma unroll
            for (int nf = 0; nf < 4; nf++) {
                int c = nf * 8 + (lane >> 2);
                int kr = kk + (lane & 3);
                b[nf][0] = bs[(size_t)kr * BST + c];
                b[nf][1] = bs[(size_t)(kr + 4) * BST + c];
            }
#pragma unroll
            for (int mf = 0; mf < 4; mf++)
#pragma unroll
                for (int nf = 0; nf < 4; nf++)
                    mma_tf32(acc[mf][nf], a[mf], b[nf]);
        }
        __syncthreads();   // protect stage 'cur' before next iteration overwrites it
    }

    // Epilogue: fragment -> global
#pragma unroll
    for (int mf = 0; mf < 4; mf++) {
        int r0 = bm + warpM * 64 + mf * 16 + (lane >> 2);
#pragma unroll
        for (int nf = 0; nf < 4; nf++) {
            int c0 = bn + warpN * 32 + nf * 8 + (lane & 3) * 2;
            C[(size_t)r0 * N + c0]           = acc[mf][nf][0];
            C[(size_t)r0 * N + c0 + 1]       = acc[mf][nf][1];
            C[(size_t)(r0 + 8) * N + c0]     = acc[mf][nf][2];
            C[(size_t)(r0 + 8) * N + c0 + 1] = acc[mf][nf][3];
        }
    }
}

// ---------------------------------------------------------------------------
// Launch
// ---------------------------------------------------------------------------
extern "C" void kernel_launch(void* const* d_in, const int* in_sizes, int n_in,
                              void* d_out, int out_size) {
    const float* x  = (const float*)d_in[0];
    const int*   gq = (const int*)d_in[1];
    const int*   gz = (const int*)d_in[2];
    const float* gs = (const float*)d_in[3];
    const int*   uq = (const int*)d_in[4];
    const int*   uz = (const int*)d_in[5];
    const float* us = (const float*)d_in[6];
    const int*   dq = (const int*)d_in[7];
    const int*   dz = (const int*)d_in[8];
    const float* ds = (const float*)d_in[9];
    float* out = (float*)d_out;

    float *wg, *wu, *wd, *xr, *gg, *uu;
    cudaGetSymbolAddress((void**)&wg, g_wg);
    cudaGetSymbolAddress((void**)&wu, g_wu);
    cudaGetSymbolAddress((void**)&wd, g_wd);
    cudaGetSymbolAddress((void**)&xr, g_xr);
    cudaGetSymbolAddress((void**)&gg, g_g);
    cudaGetSymbolAddress((void**)&uu, g_u);

    cudaFuncSetAttribute(gemm_tf32_kernel,
                         cudaFuncAttributeMaxDynamicSharedMemorySize, (int)SMEM_BYTES);

    // 1) dequant all weights (pre-rounded to tf32)
    dequant_kernel<<<dim3(INTER / 256, HIDDEN / 8), 256>>>(gq, gz, gs, wg, HIDDEN, INTER);
    dequant_kernel<<<dim3(INTER / 256, HIDDEN / 8), 256>>>(uq, uz, us, wu, HIDDEN, INTER);
    dequant_kernel<<<dim3(HIDDEN / 256, INTER / 8), 256>>>(dq, dz, ds, wd, INTER, HIDDEN);

    // 2) round x to tf32
    round_x_kernel<<<(TOKENS * HIDDEN / 4 + 255) / 256, 256>>>(x, xr, TOKENS * HIDDEN / 4);

    // 3) gate and up projections
    gemm_tf32_kernel<<<dim3(INTER / BN, TOKENS / BM), 256, SMEM_BYTES>>>(
        xr, wg, gg, TOKENS, INTER, HIDDEN);
    gemm_tf32_kernel<<<dim3(INTER / BN, TOKENS / BM), 256, SMEM_BYTES>>>(
        xr, wu, uu, TOKENS, INTER, HIDDEN);

    // 4) h = tf32(silu(g) * u), in-place over gg
    silu_mul_kernel<<<(TOKENS * INTER / 4 + 255) / 256, 256>>>(gg, uu, gg, TOKENS * INTER / 4);

    // 5) down projection -> out
    gemm_tf32_kernel<<<dim3(HIDDEN / BN, TOKENS / BM), 256, SMEM_BYTES>>>(
        gg, wd, out, TOKENS, HIDDEN, INTER);
}

// round 5
// speedup vs baseline: 1.0216x; 1.0216x over previous
#include <cuda_runtime.h>
#include <cstdint>
#include <cstddef>

// Problem dims (fixed by the dataset)
#define TOKENS 8192
#define HIDDEN 2048
#define INTER  5632

// ---------------------------------------------------------------------------
// Scratch (device globals; no allocation allowed in kernel_launch)
// ---------------------------------------------------------------------------
__device__ float g_wg[(size_t)HIDDEN * INTER];   // dequantized gate weight [H, I]
__device__ float g_wu[(size_t)HIDDEN * INTER];   // dequantized up weight   [H, I]
__device__ float g_wd[(size_t)INTER * HIDDEN];   // dequantized down weight [I, H]
__device__ float g_xr[(size_t)TOKENS * HIDDEN];  // x rounded to tf32
__device__ float g_g [(size_t)TOKENS * INTER];   // gate out, then h (in-place)
__device__ float g_u [(size_t)TOKENS * INTER];   // up out

// ---------------------------------------------------------------------------
// Helpers
// ---------------------------------------------------------------------------
__device__ __forceinline__ float to_tf32(float x) {
    float y;
    asm("cvt.rna.tf32.f32 %0, %1;" : "=f"(y) : "f"(x));
    return y;
}

__device__ __forceinline__ void cp_async16(void* smem_dst, const void* gsrc) {
    uint32_t s = (uint32_t)__cvta_generic_to_shared(smem_dst);
    asm volatile("cp.async.cg.shared.global [%0], [%1], 16;\n" :: "r"(s), "l"(gsrc));
}
__device__ __forceinline__ void cp_commit() {
    asm volatile("cp.async.commit_group;\n");
}

__device__ __forceinline__ void mma_tf32(float c[4], const float a[4], const float b[2]) {
    asm volatile(
        "mma.sync.aligned.m16n8k8.row.col.f32.tf32.tf32.f32 "
        "{%0,%1,%2,%3}, {%4,%5,%6,%7}, {%8,%9}, {%0,%1,%2,%3};\n"
        : "+f"(c[0]), "+f"(c[1]), "+f"(c[2]), "+f"(c[3])
        : "r"(__float_as_uint(a[0])), "r"(__float_as_uint(a[1])),
          "r"(__float_as_uint(a[2])), "r"(__float_as_uint(a[3])),
          "r"(__float_as_uint(b[0])), "r"(__float_as_uint(b[1])));
}

// ---------------------------------------------------------------------------
// GPTQ int4 dequant: w[k,o] = (q[k,o] - (z[g,o] + 1)) * s[g,o], group = k/128
// Output [K, N] row-major, pre-rounded to tf32.
// ---------------------------------------------------------------------------
__global__ void dequant_kernel(const int* __restrict__ qw,
                               const int* __restrict__ qz,
                               const float* __restrict__ sc,
                               float* __restrict__ w,
                               int in_dim, int out) {
    int o = blockIdx.x * blockDim.x + threadIdx.x;
    int kp = blockIdx.y;               // packed row index: covers k = kp*8 .. kp*8+7
    if (o >= out) return;
    int grp = kp >> 4;                 // (kp*8)/128
    unsigned q = (unsigned)qw[(size_t)kp * out + o];
    unsigned zw = (unsigned)qz[(size_t)grp * (out >> 3) + (o >> 3)];
    int z = (int)((zw >> ((o & 7) * 4)) & 0xF) + 1;
    float s = sc[(size_t)grp * out + o];
#pragma unroll
    for (int j = 0; j < 8; j++) {
        int qv = (int)((q >> (4 * j)) & 0xF);
        w[(size_t)(kp * 8 + j) * out + o] = to_tf32((float)(qv - z) * s);
    }
}

// Round x to tf32 (vectorized)
__global__ void round_x_kernel(const float* __restrict__ x, float* __restrict__ y, int n4) {
    int i = blockIdx.x * blockDim.x + threadIdx.x;
    if (i >= n4) return;
    float4 v = reinterpret_cast<const float4*>(x)[i];
    v.x = to_tf32(v.x); v.y = to_tf32(v.y); v.z = to_tf32(v.z); v.w = to_tf32(v.w);
    reinterpret_cast<float4*>(y)[i] = v;
}

// h = tf32_round( silu(g) * u )   (h aliases g)
__global__ void silu_mul_kernel(const float* __restrict__ g, const float* __restrict__ u,
                                float* __restrict__ h, int n4) {
    int i = blockIdx.x * blockDim.x + threadIdx.x;
    if (i >= n4) return;
    float4 gv = reinterpret_cast<const float4*>(g)[i];
    float4 uv = reinterpret_cast<const float4*>(u)[i];
    float4 o;
    o.x = to_tf32(gv.x / (1.0f + __expf(-gv.x)) * uv.x);
    o.y = to_tf32(gv.y / (1.0f + __expf(-gv.y)) * uv.y);
    o.z = to_tf32(gv.z / (1.0f + __expf(-gv.z)) * uv.z);
    o.w = to_tf32(gv.w / (1.0f + __expf(-gv.w)) * uv.w);
    reinterpret_cast<float4*>(h)[i] = o;
}

// ---------------------------------------------------------------------------
// tf32 GEMM: C[M,N] = A[M,K] @ B[K,N]  (fp32 storage, tf32 math)
// CTA tile 128x256, BK=32, 256 threads = 8 warps as 2(M) x 4(N), warp 64x64.
// 3-stage cp.async pipeline. Conflict-free smem layouts for both operands.
// ---------------------------------------------------------------------------
constexpr int BM = 128, BN = 256, BK = 32, STAGES = 3;
constexpr int AST = BK + 4;    // 36 floats/row: bank stride 4 -> A frags conflict-free
constexpr int BST = BN + 8;    // 264 floats/row: bank stride 8 -> B frags conflict-free
constexpr int SMEM_FLOATS = STAGES * (BM * AST + BK * BST);
constexpr size_t SMEM_BYTES = (size_t)SMEM_FLOATS * 4;   // 156,672 B

__global__ void __launch_bounds__(256, 1)
gemm_tf32_kernel(const float* __restrict__ A, const float* __restrict__ B,
                 float* __restrict__ C, int M, int N, int K) {
    extern __shared__ float smem[];
    float* As = smem;
    float* Bs = smem + STAGES * BM * AST;

    const int tid  = threadIdx.x;
    const int lane = tid & 31;
    const int wid  = tid >> 5;
    const int warpM = wid & 1;     // 0..1
    const int warpN = wid >> 1;    // 0..3
    const int bm = blockIdx.y * BM;
    const int bn = blockIdx.x * BN;

    // Global->smem mapping:
    // A tile 128x32 floats = 128 rows x 8 float4  -> 4 chunks/thread
    // B tile 32x256 floats = 32 rows x 64 float4  -> 8 chunks/thread
    const int af4 = tid & 7;       // float4 col in A row
    const int ar0 = tid >> 3;      // 0..31, rows ar0 + {0,32,64,96}
    const int bf4 = tid & 31;      // float4 col (0..31), cols bf4 + {0,32}
    const int br0 = tid >> 5;      // 0..7, rows br0 + {0,8,16,24}

    auto load_stage = [&](int st, int k0) {
        float* as = As + st * BM * AST;
        float* bs = Bs + st * BK * BST;
#pragma unroll
        for (int i = 0; i < 4; i++) {
            int r = ar0 + i * 32;
            cp_async16(as + r * AST + af4 * 4,
                       A + (size_t)(bm + r) * K + k0 + af4 * 4);
        }
#pragma unroll
        for (int i = 0; i < 4; i++) {
            int r = br0 + i * 8;
#pragma unroll
            for (int j = 0; j < 2; j++) {
                int c4 = bf4 + j * 32;
                cp_async16(bs + r * BST + c4 * 4,
                           B + (size_t)(k0 + r) * N + bn + c4 * 4);
            }
        }
        cp_commit();
    };

    float acc[4][8][4];
#pragma unroll
    for (int mf = 0; mf < 4; mf++)
#pragma unroll
        for (int nf = 0; nf < 8; nf++)
#pragma unroll
            for (int i = 0; i < 4; i++) acc[mf][nf][i] = 0.0f;

    const int kTiles = K / BK;
    load_stage(0, 0);
    load_stage(1, BK);

    for (int kt = 0; kt < kTiles; ++kt) {
        // Issue the load 2 stages ahead (its slot was consumed in iter kt-1,
        // and the barrier at the end of iter kt-1 protects it), then wait for
        // stage kt to land.
        if (kt + 2 < kTiles) {
            load_stage((kt + 2) % STAGES, (kt + 2) * BK);
            asm volatile("cp.async.wait_group 2;\n");
        } else {
            asm volatile("cp.async.wait_group 0;\n");
        }
        __syncthreads();

        const int cur = kt % STAGES;
        const float* as = As + cur * BM * AST + (warpM * 64) * AST;
        const float* bs = Bs + cur * BK * BST + warpN * 64;
#pragma unroll
        for (int kk = 0; kk < BK; kk += 8) {
            float a[4][4];
            float b[8][2];
#pragma unroll
            for (int mf = 0; mf < 4; mf++) {
                int r = mf * 16 + (lane >> 2);
                int kc = kk + (lane & 3);
                a[mf][0] = as[(size_t)r * AST + kc];
                a[mf][1] = as[(size_t)(r + 8) * AST + kc];
                a[mf][2] = as[(size_t)r * AST + kc + 4];
                a[mf][3] = as[(size_t)(r + 8) * AST + kc + 4];
            }
#pragma unroll
            for (int nf = 0; nf < 8; nf++) {
                int c = nf * 8 + (lane >> 2);
                int kr = kk + (lane & 3);
                b[nf][0] = bs[(size_t)kr * BST + c];
                b[nf][1] = bs[(size_t)(kr + 4) * BST + c];
            }
#pragma unroll
            for (int mf = 0; mf < 4; mf++)
#pragma unroll
                for (int nf = 0; nf < 8; nf++)
                    mma_tf32(acc[mf][nf], a[mf], b[nf]);
        }
        __syncthreads();   // protect stage slots before the next prefetch
    }

    // Epilogue: fragment -> global (float2 stores, coalesced within quads)
#pragma unroll
    for (int mf = 0; mf < 4; mf++) {
        int r0 = bm + warpM * 64 + mf * 16 + (lane >> 2);
#pragma unroll
        for (int nf = 0; nf < 8; nf++) {
            int c0 = bn + warpN * 64 + nf * 8 + (lane & 3) * 2;
            *reinterpret_cast<float2*>(C + (size_t)r0 * N + c0) =
                make_float2(acc[mf][nf][0], acc[mf][nf][1]);
            *reinterpret_cast<float2*>(C + (size_t)(r0 + 8) * N + c0) =
                make_float2(acc[mf][nf][2], acc[mf][nf][3]);
        }
    }
}

// ---------------------------------------------------------------------------
// Launch
// ---------------------------------------------------------------------------
extern "C" void kernel_launch(void* const* d_in, const int* in_sizes, int n_in,
                              void* d_out, int out_size) {
    const float* x  = (const float*)d_in[0];
    const int*   gq = (const int*)d_in[1];
    const int*   gz = (const int*)d_in[2];
    const float* gs = (const float*)d_in[3];
    const int*   uq = (const int*)d_in[4];
    const int*   uz = (const int*)d_in[5];
    const float* us = (const float*)d_in[6];
    const int*   dq = (const int*)d_in[7];
    const int*   dz = (const int*)d_in[8];
    const float* ds = (const float*)d_in[9];
    float* out = (float*)d_out;

    float *wg, *wu, *wd, *xr, *gg, *uu;
    cudaGetSymbolAddress((void**)&wg, g_wg);
    cudaGetSymbolAddress((void**)&wu, g_wu);
    cudaGetSymbolAddress((void**)&wd, g_wd);
    cudaGetSymbolAddress((void**)&xr, g_xr);
    cudaGetSymbolAddress((void**)&gg, g_g);
    cudaGetSymbolAddress((void**)&uu, g_u);

    cudaFuncSetAttribute(gemm_tf32_kernel,
                         cudaFuncAttributeMaxDynamicSharedMemorySize, (int)SMEM_BYTES);

    // 1) dequant all weights (pre-rounded to tf32), natural [K, N] layout
    dequant_kernel<<<dim3(INTER / 256, HIDDEN / 8), 256>>>(gq, gz, gs, wg, HIDDEN, INTER);
    dequant_kernel<<<dim3(INTER / 256, HIDDEN / 8), 256>>>(uq, uz, us, wu, HIDDEN, INTER);
    dequant_kernel<<<dim3(HIDDEN / 256, INTER / 8), 256>>>(dq, dz, ds, wd, INTER, HIDDEN);

    // 2) round x to tf32
    round_x_kernel<<<(TOKENS * HIDDEN / 4 + 255) / 256, 256>>>(x, xr, TOKENS * HIDDEN / 4);

    // 3) gate and up projections
    gemm_tf32_kernel<<<dim3(INTER / BN, TOKENS / BM), 256, SMEM_BYTES>>>(
        xr, wg, gg, TOKENS, INTER, HIDDEN);
    gemm_tf32_kernel<<<dim3(INTER / BN, TOKENS / BM), 256, SMEM_BYTES>>>(
        xr, wu, uu, TOKENS, INTER, HIDDEN);

    // 4) h = tf32(silu(g) * u), in-place over gg
    silu_mul_kernel<<<(TOKENS * INTER / 4 + 255) / 256, 256>>>(gg, uu, gg, TOKENS * INTER / 4);

    // 5) down projection -> out
    gemm_tf32_kernel<<<dim3(HIDDEN / BN, TOKENS / BM), 256, SMEM_BYTES>>>(
        gg, wd, out, TOKENS, HIDDEN, INTER);
}

// round 6
// speedup vs baseline: 1.6907x; 1.6549x over previous
#include <cuda_runtime.h>
#include <cuda_fp16.h>
#include <cstdint>
#include <cstddef>

// Problem dims (fixed by the dataset)
#define TOKENS 8192
#define HIDDEN 2048
#define INTER  5632

// ---------------------------------------------------------------------------
// Scratch (device globals; no allocation allowed in kernel_launch)
// ---------------------------------------------------------------------------
__device__ __half g_wg[(size_t)HIDDEN * INTER];   // gate weight [H, I] fp16
__device__ __half g_wu[(size_t)HIDDEN * INTER];   // up weight   [H, I] fp16
__device__ __half g_wd[(size_t)INTER * HIDDEN];   // down weight [I, H] fp16
__device__ __half g_xh[(size_t)TOKENS * HIDDEN];  // x in fp16
__device__ float  g_g [(size_t)TOKENS * INTER];   // gate GEMM out (fp32)
__device__ float  g_u [(size_t)TOKENS * INTER];   // up GEMM out (fp32)
__device__ __half g_h [(size_t)TOKENS * INTER];   // silu(g)*u in fp16

// ---------------------------------------------------------------------------
// Helpers
// ---------------------------------------------------------------------------
__device__ __forceinline__ void cp_async16(void* smem_dst, const void* gsrc) {
    uint32_t s = (uint32_t)__cvta_generic_to_shared(smem_dst);
    asm volatile("cp.async.cg.shared.global [%0], [%1], 16;\n" :: "r"(s), "l"(gsrc));
}
__device__ __forceinline__ void cp_commit() {
    asm volatile("cp.async.commit_group;\n");
}

__device__ __forceinline__ void ldmA(uint32_t r[4], uint32_t addr) {
    asm volatile("ldmatrix.sync.aligned.m8n8.x4.shared.b16 {%0,%1,%2,%3}, [%4];"
                 : "=r"(r[0]), "=r"(r[1]), "=r"(r[2]), "=r"(r[3]) : "r"(addr));
}
__device__ __forceinline__ void ldmB(uint32_t r[2], uint32_t addr) {
    asm volatile("ldmatrix.sync.aligned.m8n8.x2.trans.shared.b16 {%0,%1}, [%2];"
                 : "=r"(r[0]), "=r"(r[1]) : "r"(addr));
}

__device__ __forceinline__ void mma_f16(float c[4], const uint32_t a[4], const uint32_t b[2]) {
    asm volatile(
        "mma.sync.aligned.m16n8k16.row.col.f32.f16.f16.f32 "
        "{%0,%1,%2,%3}, {%4,%5,%6,%7}, {%8,%9}, {%0,%1,%2,%3};\n"
        : "+f"(c[0]), "+f"(c[1]), "+f"(c[2]), "+f"(c[3])
        : "r"(a[0]), "r"(a[1]), "r"(a[2]), "r"(a[3]),
          "r"(b[0]), "r"(b[1]));
}

// ---------------------------------------------------------------------------
// GPTQ int4 dequant: w[k,o] = (q[k,o] - (z[g,o] + 1)) * s[g,o], group = k/128
// Output [K, N] row-major fp16.
// ---------------------------------------------------------------------------
__global__ void dequant_kernel(const int* __restrict__ qw,
                               const int* __restrict__ qz,
                               const float* __restrict__ sc,
                               __half* __restrict__ w,
                               int in_dim, int out) {
    int o = blockIdx.x * blockDim.x + threadIdx.x;
    int kp = blockIdx.y;               // packed row index: covers k = kp*8 .. kp*8+7
    if (o >= out) return;
    int grp = kp >> 4;                 // (kp*8)/128
    unsigned q = (unsigned)qw[(size_t)kp * out + o];
    unsigned zw = (unsigned)qz[(size_t)grp * (out >> 3) + (o >> 3)];
    int z = (int)((zw >> ((o & 7) * 4)) & 0xF) + 1;
    float s = sc[(size_t)grp * out + o];
#pragma unroll
    for (int j = 0; j < 8; j++) {
        int qv = (int)((q >> (4 * j)) & 0xF);
        w[(size_t)(kp * 8 + j) * out + o] = __float2half_rn((float)(qv - z) * s);
    }
}

// Convert x to fp16 (8 floats / thread)
__global__ void x_to_half_kernel(const float* __restrict__ x, __half* __restrict__ y, int n8) {
    int i = blockIdx.x * blockDim.x + threadIdx.x;
    if (i >= n8) return;
    float4 v0 = reinterpret_cast<const float4*>(x)[2 * i];
    float4 v1 = reinterpret_cast<const float4*>(x)[2 * i + 1];
    __half2 h[4];
    h[0] = __floats2half2_rn(v0.x, v0.y);
    h[1] = __floats2half2_rn(v0.z, v0.w);
    h[2] = __floats2half2_rn(v1.x, v1.y);
    h[3] = __floats2half2_rn(v1.z, v1.w);
    reinterpret_cast<uint4*>(y)[i] = *reinterpret_cast<uint4*>(h);
}

// h = fp16( silu(g) * u )
__global__ void silu_mul_kernel(const float* __restrict__ g, const float* __restrict__ u,
                                __half* __restrict__ h, int n4) {
    int i = blockIdx.x * blockDim.x + threadIdx.x;
    if (i >= n4) return;
    float4 gv = reinterpret_cast<const float4*>(g)[i];
    float4 uv = reinterpret_cast<const float4*>(u)[i];
    float o0 = gv.x / (1.0f + __expf(-gv.x)) * uv.x;
    float o1 = gv.y / (1.0f + __expf(-gv.y)) * uv.y;
    float o2 = gv.z / (1.0f + __expf(-gv.z)) * uv.z;
    float o3 = gv.w / (1.0f + __expf(-gv.w)) * uv.w;
    __half2 p[2];
    p[0] = __floats2half2_rn(o0, o1);
    p[1] = __floats2half2_rn(o2, o3);
    reinterpret_cast<uint2*>(h)[i] = *reinterpret_cast<uint2*>(p);
}

// ---------------------------------------------------------------------------
// fp16 GEMM: C[M,N] = A[M,K] @ B[K,N]  (fp16 storage, fp32 accum)
// CTA tile 128x256, BK=32, 256 threads = 8 warps as 2(M) x 4(N), warp 64x64.
// 4-stage cp.async pipeline, ldmatrix fragment loads, m16n8k16 MMA.
// ---------------------------------------------------------------------------
constexpr int BM = 128, BN = 256, BK = 32, STAGES = 4;
constexpr int AST = 40;    // halves per A row (80B): stride 20 banks -> conflict-free ldmatrix
constexpr int BST = 264;   // halves per B row (528B): 16B rotation per row -> conflict-free
constexpr int A_STAGE = BM * AST;   // halves
constexpr int B_STAGE = BK * BST;   // halves
constexpr size_t SMEM_BYTES = (size_t)STAGES * (A_STAGE + B_STAGE) * 2;  // 108,544 B

__global__ void __launch_bounds__(256, 1)
gemm_f16_kernel(const __half* __restrict__ A, const __half* __restrict__ B,
                float* __restrict__ C, int M, int N, int K) {
    extern __shared__ __half smem[];
    __half* As = smem;
    __half* Bs = smem + STAGES * A_STAGE;
    const uint32_t As_u = (uint32_t)__cvta_generic_to_shared(As);
    const uint32_t Bs_u = (uint32_t)__cvta_generic_to_shared(Bs);

    const int tid  = threadIdx.x;
    const int lane = tid & 31;
    const int wid  = tid >> 5;
    const int warpM = wid & 1;     // 0..1
    const int warpN = wid >> 1;    // 0..3
    const int bm = blockIdx.y * BM;
    const int bn = blockIdx.x * BN;

    // Global->smem mapping (16B chunks = 8 halves):
    // A tile 128x32 halves = 128 rows x 4 chunks -> 2 chunks/thread
    const int af8 = tid & 3;       // chunk in A row
    const int ar0 = tid >> 2;      // 0..63, rows ar0 + {0,64}
    // B tile 32x256 halves = 32 rows x 32 chunks -> 4 chunks/thread
    const int bf8 = tid & 31;      // chunk in B row
    const int br0 = tid >> 5;      // 0..7, rows br0 + {0,8,16,24}

    auto load_stage = [&](int st, int k0) {
        __half* as = As + st * A_STAGE;
        __half* bs = Bs + st * B_STAGE;
#pragma unroll
        for (int i = 0; i < 2; i++) {
            int r = ar0 + i * 64;
            cp_async16(as + r * AST + af8 * 8,
                       A + (size_t)(bm + r) * K + k0 + af8 * 8);
        }
#pragma unroll
        for (int i = 0; i < 4; i++) {
            int r = br0 + i * 8;
            cp_async16(bs + r * BST + bf8 * 8,
                       B + (size_t)(k0 + r) * N + bn + bf8 * 8);
        }
        cp_commit();
    };

    float acc[4][8][4];
#pragma unroll
    for (int mf = 0; mf < 4; mf++)
#pragma unroll
        for (int nf = 0; nf < 8; nf++)
#pragma unroll
            for (int i = 0; i < 4; i++) acc[mf][nf][i] = 0.0f;

    const int kTiles = K / BK;
    load_stage(0, 0);
    load_stage(1, BK);
    load_stage(2, 2 * BK);

    // ldmatrix per-lane address components (in halves)
    const int a_row_in_warp = warpM * 64 + (lane & 15);     // + mf*16
    const int a_col_k8 = (lane >> 4) * 8;                   // + kk
    const int b_row_k = lane & 15;                          // + kk
    const int b_col = warpN * 64;                           // + nf*8

    for (int kt = 0; kt < kTiles; ++kt) {
        if (kt + 3 < kTiles) {
            load_stage((kt + 3) % STAGES, (kt + 3) * BK);
            asm volatile("cp.async.wait_group 3;\n");
        } else {
            asm volatile("cp.async.wait_group 0;\n");
        }
        __syncthreads();

        const int cur = kt % STAGES;
        const uint32_t as_base = As_u + (uint32_t)(cur * A_STAGE) * 2;
        const uint32_t bs_base = Bs_u + (uint32_t)(cur * B_STAGE) * 2;

#pragma unroll
        for (int kk = 0; kk < BK; kk += 16) {
            uint32_t a[4][4];
            uint32_t b[8][2];
#pragma unroll
            for (int mf = 0; mf < 4; mf++) {
                uint32_t addr = as_base +
                    ((uint32_t)(a_row_in_warp + mf * 16) * AST + kk + a_col_k8) * 2;
                ldmA(a[mf], addr);
            }
#pragma unroll
            for (int nf = 0; nf < 8; nf++) {
                uint32_t addr = bs_base +
                    ((uint32_t)(b_row_k + kk) * BST + b_col + nf * 8) * 2;
                ldmB(b[nf], addr);
            }
#pragma unroll
            for (int mf = 0; mf < 4; mf++)
#pragma unroll
                for (int nf = 0; nf < 8; nf++)
                    mma_f16(acc[mf][nf], a[mf], b[nf]);
        }
        __syncthreads();   // protect stage slots before the next prefetch
    }

    // Epilogue: fragment -> global (float2 stores)
#pragma unroll
    for (int mf = 0; mf < 4; mf++) {
        int r0 = bm + warpM * 64 + mf * 16 + (lane >> 2);
#pragma unroll
        for (int nf = 0; nf < 8; nf++) {
            int c0 = bn + warpN * 64 + nf * 8 + (lane & 3) * 2;
            *reinterpret_cast<float2*>(C + (size_t)r0 * N + c0) =
                make_float2(acc[mf][nf][0], acc[mf][nf][1]);
            *reinterpret_cast<float2*>(C + (size_t)(r0 + 8) * N + c0) =
                make_float2(acc[mf][nf][2], acc[mf][nf][3]);
        }
    }
}

// ---------------------------------------------------------------------------
// Launch
// ---------------------------------------------------------------------------
extern "C" void kernel_launch(void* const* d_in, const int* in_sizes, int n_in,
                              void* d_out, int out_size) {
    const float* x  = (const float*)d_in[0];
    const int*   gq = (const int*)d_in[1];
    const int*   gz = (const int*)d_in[2];
    const float* gs = (const float*)d_in[3];
    const int*   uq = (const int*)d_in[4];
    const int*   uz = (const int*)d_in[5];
    const float* us = (const float*)d_in[6];
    const int*   dq = (const int*)d_in[7];
    const int*   dz = (const int*)d_in[8];
    const float* ds = (const float*)d_in[9];
    float* out = (float*)d_out;

    __half *wg, *wu, *wd, *xh, *hh;
    float *gg, *uu;
    cudaGetSymbolAddress((void**)&wg, g_wg);
    cudaGetSymbolAddress((void**)&wu, g_wu);
    cudaGetSymbolAddress((void**)&wd, g_wd);
    cudaGetSymbolAddress((void**)&xh, g_xh);
    cudaGetSymbolAddress((void**)&gg, g_g);
    cudaGetSymbolAddress((void**)&uu, g_u);
    cudaGetSymbolAddress((void**)&hh, g_h);

    cudaFuncSetAttribute(gemm_f16_kernel,
                         cudaFuncAttributeMaxDynamicSharedMemorySize, (int)SMEM_BYTES);

    // 1) dequant all weights to fp16, natural [K, N] layout
    dequant_kernel<<<dim3(INTER / 256, HIDDEN / 8), 256>>>(gq, gz, gs, wg, HIDDEN, INTER);
    dequant_kernel<<<dim3(INTER / 256, HIDDEN / 8), 256>>>(uq, uz, us, wu, HIDDEN, INTER);
    dequant_kernel<<<dim3(HIDDEN / 256, INTER / 8), 256>>>(dq, dz, ds, wd, INTER, HIDDEN);

    // 2) x to fp16
    x_to_half_kernel<<<(TOKENS * HIDDEN / 8 + 255) / 256, 256>>>(x, xh, TOKENS * HIDDEN / 8);

    // 3) gate and up projections (fp32 out)
    gemm_f16_kernel<<<dim3(INTER / BN, TOKENS / BM), 256, SMEM_BYTES>>>(
        xh, wg, gg, TOKENS, INTER, HIDDEN);
    gemm_f16_kernel<<<dim3(INTER / BN, TOKENS / BM), 256, SMEM_BYTES>>>(
        xh, wu, uu, TOKENS, INTER, HIDDEN);

    // 4) h = fp16(silu(g) * u)
    silu_mul_kernel<<<(TOKENS * INTER / 4 + 255) / 256, 256>>>(gg, uu, hh, TOKENS * INTER / 4);

    // 5) down projection -> out (fp32)
    gemm_f16_kernel<<<dim3(HIDDEN / BN, TOKENS / BM), 256, SMEM_BYTES>>>(
        hh, wd, out, TOKENS, HIDDEN, INTER);
}

// round 7
// speedup vs baseline: 1.8208x; 1.0770x over previous
#include <cuda_runtime.h>
#include <cuda_fp16.h>
#include <cstdint>
#include <cstddef>

// Problem dims (fixed by the dataset)
#define TOKENS 8192
#define HIDDEN 2048
#define INTER  5632

// ---------------------------------------------------------------------------
// Scratch (device globals; no allocation allowed in kernel_launch)
// ---------------------------------------------------------------------------
__device__ __half g_wg[(size_t)HIDDEN * INTER];   // gate weight [H, I] fp16
__device__ __half g_wu[(size_t)HIDDEN * INTER];   // up weight   [H, I] fp16
__device__ __half g_wd[(size_t)INTER * HIDDEN];   // down weight [I, H] fp16
__device__ __half g_xh[(size_t)TOKENS * HIDDEN];  // x in fp16
__device__ __half g_h [(size_t)TOKENS * INTER];   // silu(xWg)*(xWu) in fp16

// ---------------------------------------------------------------------------
// Helpers
// ---------------------------------------------------------------------------
__device__ __forceinline__ void cp_async16(void* smem_dst, const void* gsrc) {
    uint32_t s = (uint32_t)__cvta_generic_to_shared(smem_dst);
    asm volatile("cp.async.cg.shared.global [%0], [%1], 16;\n" :: "r"(s), "l"(gsrc));
}
__device__ __forceinline__ void cp_commit() {
    asm volatile("cp.async.commit_group;\n");
}

__device__ __forceinline__ void ldmA(uint32_t r[4], uint32_t addr) {
    asm volatile("ldmatrix.sync.aligned.m8n8.x4.shared.b16 {%0,%1,%2,%3}, [%4];"
                 : "=r"(r[0]), "=r"(r[1]), "=r"(r[2]), "=r"(r[3]) : "r"(addr));
}
// x4 trans: returns {k0-7/n0-7, k8-15/n0-7, k0-7/n8-15, k8-15/n8-15}
__device__ __forceinline__ void ldmB4(uint32_t r[4], uint32_t addr) {
    asm volatile("ldmatrix.sync.aligned.m8n8.x4.trans.shared.b16 {%0,%1,%2,%3}, [%4];"
                 : "=r"(r[0]), "=r"(r[1]), "=r"(r[2]), "=r"(r[3]) : "r"(addr));
}

__device__ __forceinline__ void mma_f16(float c[4], const uint32_t a[4], const uint32_t* b) {
    asm volatile(
        "mma.sync.aligned.m16n8k16.row.col.f32.f16.f16.f32 "
        "{%0,%1,%2,%3}, {%4,%5,%6,%7}, {%8,%9}, {%0,%1,%2,%3};\n"
        : "+f"(c[0]), "+f"(c[1]), "+f"(c[2]), "+f"(c[3])
        : "r"(a[0]), "r"(a[1]), "r"(a[2]), "r"(a[3]),
          "r"(b[0]), "r"(b[1]));
}

__device__ __forceinline__ float silu(float v) {
    return v / (1.0f + __expf(-v));
}

// ---------------------------------------------------------------------------
// GPTQ int4 dequant -> fp16 [K, N] row-major
// ---------------------------------------------------------------------------
__global__ void dequant_kernel(const int* __restrict__ qw,
                               const int* __restrict__ qz,
                               const float* __restrict__ sc,
                               __half* __restrict__ w,
                               int in_dim, int out) {
    int o = blockIdx.x * blockDim.x + threadIdx.x;
    int kp = blockIdx.y;
    if (o >= out) return;
    int grp = kp >> 4;
    unsigned q = (unsigned)qw[(size_t)kp * out + o];
    unsigned zw = (unsigned)qz[(size_t)grp * (out >> 3) + (o >> 3)];
    int z = (int)((zw >> ((o & 7) * 4)) & 0xF) + 1;
    float s = sc[(size_t)grp * out + o];
#pragma unroll
    for (int j = 0; j < 8; j++) {
        int qv = (int)((q >> (4 * j)) & 0xF);
        w[(size_t)(kp * 8 + j) * out + o] = __float2half_rn((float)(qv - z) * s);
    }
}

// Convert x to fp16 (8 floats / thread)
__global__ void x_to_half_kernel(const float* __restrict__ x, __half* __restrict__ y, int n8) {
    int i = blockIdx.x * blockDim.x + threadIdx.x;
    if (i >= n8) return;
    float4 v0 = reinterpret_cast<const float4*>(x)[2 * i];
    float4 v1 = reinterpret_cast<const float4*>(x)[2 * i + 1];
    __half2 h[4];
    h[0] = __floats2half2_rn(v0.x, v0.y);
    h[1] = __floats2half2_rn(v0.z, v0.w);
    h[2] = __floats2half2_rn(v1.x, v1.y);
    h[3] = __floats2half2_rn(v1.z, v1.w);
    reinterpret_cast<uint4*>(y)[i] = *reinterpret_cast<uint4*>(h);
}

// ---------------------------------------------------------------------------
// Fused gate+up GEMM: h = fp16( silu(A@Bg) * (A@Bu) ), A[M,K], B*[K,N]
// CTA tile 128x128 (both matrices), BK=32, 256 threads, 8 warps 2(M)x4(N),
// warp tile 64x32 per matrix. 4-stage cp.async pipeline.
// ---------------------------------------------------------------------------
constexpr int FBM = 128, FBN = 128, FBK = 32, FSTAGES = 4;
constexpr int FAST = 40;                 // halves per A row
constexpr int FBST = 136;                // halves per B row (272B)
constexpr int FA_STAGE = FBM * FAST;     // 5120 halves
constexpr int FB_STAGE = FBK * FBST;     // 4352 halves
constexpr size_t FSMEM_BYTES = (size_t)FSTAGES * (FA_STAGE + 2 * FB_STAGE) * 2; // 110,592

__global__ void __launch_bounds__(256, 1)
fused_gateup_kernel(const __half* __restrict__ A,
                    const __half* __restrict__ Bg,
                    const __half* __restrict__ Bu,
                    __half* __restrict__ H, int M, int N, int K) {
    extern __shared__ __half smem[];
    __half* As  = smem;
    __half* Bgs = smem + FSTAGES * FA_STAGE;
    __half* Bus = Bgs + FSTAGES * FB_STAGE;
    const uint32_t As_u  = (uint32_t)__cvta_generic_to_shared(As);
    const uint32_t Bgs_u = (uint32_t)__cvta_generic_to_shared(Bgs);
    const uint32_t Bus_u = (uint32_t)__cvta_generic_to_shared(Bus);

    const int tid  = threadIdx.x;
    const int lane = tid & 31;
    const int wid  = tid >> 5;
    const int warpM = wid & 1;     // 0..1
    const int warpN = wid >> 1;    // 0..3
    const int bm = blockIdx.y * FBM;
    const int bn = blockIdx.x * FBN;

    // cp.async mapping (16B chunks):
    const int af8 = tid & 3;       // A: 4 chunks/row, rows tid>>2 + {0,64}
    const int ar0 = tid >> 2;
    const int bf8 = tid & 15;      // B: 16 chunks/row, rows tid>>4 + {0,16}
    const int br0 = tid >> 4;

    auto load_stage = [&](int st, int k0) {
        __half* as = As + st * FA_STAGE;
        __half* bgs = Bgs + st * FB_STAGE;
        __half* bus = Bus + st * FB_STAGE;
#pragma unroll
        for (int i = 0; i < 2; i++) {
            int r = ar0 + i * 64;
            cp_async16(as + r * FAST + af8 * 8,
                       A + (size_t)(bm + r) * K + k0 + af8 * 8);
        }
#pragma unroll
        for (int i = 0; i < 2; i++) {
            int r = br0 + i * 16;
            cp_async16(bgs + r * FBST + bf8 * 8,
                       Bg + (size_t)(k0 + r) * N + bn + bf8 * 8);
            cp_async16(bus + r * FBST + bf8 * 8,
                       Bu + (size_t)(k0 + r) * N + bn + bf8 * 8);
        }
        cp_commit();
    };

    float accg[4][4][4], accu[4][4][4];
#pragma unroll
    for (int mf = 0; mf < 4; mf++)
#pragma unroll
        for (int nf = 0; nf < 4; nf++)
#pragma unroll
            for (int i = 0; i < 4; i++) { accg[mf][nf][i] = 0.0f; accu[mf][nf][i] = 0.0f; }

    const int kTiles = K / FBK;
    load_stage(0, 0);
    load_stage(1, FBK);
    load_stage(2, 2 * FBK);

    // Fragment addressing
    const int a_row = warpM * 64 + (lane & 15);
    const int a_k8  = (lane >> 4) * 8;
    const int b_row = (lane & 7) | (((lane >> 3) & 1) << 3);   // k offset 0..15
    const int b_col = warpN * 32 + ((lane >> 4) & 1) * 8;      // + q*16

    for (int kt = 0; kt < kTiles; ++kt) {
        if (kt + 3 < kTiles) {
            load_stage((kt + 3) % FSTAGES, (kt + 3) * FBK);
            asm volatile("cp.async.wait_group 3;\n");
        } else {
            asm volatile("cp.async.wait_group 0;\n");
        }
        __syncthreads();

        const int cur = kt % FSTAGES;
        const uint32_t as_base = As_u + (uint32_t)(cur * FA_STAGE) * 2;
        const uint32_t bg_base = Bgs_u + (uint32_t)(cur * FB_STAGE) * 2;
        const uint32_t bu_base = Bus_u + (uint32_t)(cur * FB_STAGE) * 2;

#pragma unroll
        for (int kk = 0; kk < FBK; kk += 16) {
            uint32_t a[4][4];
            uint32_t bg[4][4];   // [q][4] -> frags: nf=2q -> bg[q]+0, nf=2q+1 -> bg[q]+2
            uint32_t bu[4][4];
#pragma unroll
            for (int mf = 0; mf < 4; mf++) {
                uint32_t addr = as_base +
                    ((uint32_t)(a_row + mf * 16) * FAST + kk + a_k8) * 2;
                ldmA(a[mf], addr);
            }
#pragma unroll
            for (int q = 0; q < 2; q++) {
                uint32_t off = ((uint32_t)(kk + b_row) * FBST + b_col + q * 16) * 2;
                ldmB4(bg[q], bg_base + off);
                ldmB4(bu[q], bu_base + off);
            }
#pragma unroll
            for (int mf = 0; mf < 4; mf++)
#pragma unroll
                for (int nf = 0; nf < 4; nf++) {
                    mma_f16(accg[mf][nf], a[mf], &bg[nf >> 1][(nf & 1) * 2]);
                    mma_f16(accu[mf][nf], a[mf], &bu[nf >> 1][(nf & 1) * 2]);
                }
        }
        __syncthreads();
    }

    // Epilogue: h = fp16(silu(g)*u)
#pragma unroll
    for (int mf = 0; mf < 4; mf++) {
        int r0 = bm + warpM * 64 + mf * 16 + (lane >> 2);
#pragma unroll
        for (int nf = 0; nf < 4; nf++) {
            int c0 = bn + warpN * 32 + nf * 8 + (lane & 3) * 2;
            float* g = accg[mf][nf];
            float* u = accu[mf][nf];
            *reinterpret_cast<__half2*>(H + (size_t)r0 * N + c0) =
                __floats2half2_rn(silu(g[0]) * u[0], silu(g[1]) * u[1]);
            *reinterpret_cast<__half2*>(H + (size_t)(r0 + 8) * N + c0) =
                __floats2half2_rn(silu(g[2]) * u[2], silu(g[3]) * u[3]);
        }
    }
}

// ---------------------------------------------------------------------------
// fp16 GEMM (down proj): C[M,N] = A[M,K] @ B[K,N], fp32 out
// CTA tile 128x256, BK=32, 256 threads, warp 64x64, 4 stages.
// ---------------------------------------------------------------------------
constexpr int BM = 128, BN = 256, BK = 32, STAGES = 4;
constexpr int AST = 40;
constexpr int BST = 264;
constexpr int A_STAGE = BM * AST;
constexpr int B_STAGE = BK * BST;
constexpr size_t SMEM_BYTES = (size_t)STAGES * (A_STAGE + B_STAGE) * 2;  // 108,544

__global__ void __launch_bounds__(256, 1)
gemm_f16_kernel(const __half* __restrict__ A, const __half* __restrict__ B,
                float* __restrict__ C, int M, int N, int K) {
    extern __shared__ __half smem[];
    __half* As = smem;
    __half* Bs = smem + STAGES * A_STAGE;
    const uint32_t As_u = (uint32_t)__cvta_generic_to_shared(As);
    const uint32_t Bs_u = (uint32_t)__cvta_generic_to_shared(Bs);

    const int tid  = threadIdx.x;
    const int lane = tid & 31;
    const int wid  = tid >> 5;
    const int warpM = wid & 1;
    const int warpN = wid >> 1;
    const int bm = blockIdx.y * BM;
    const int bn = blockIdx.x * BN;

    const int af8 = tid & 3;
    const int ar0 = tid >> 2;
    const int bf8 = tid & 31;
    const int br0 = tid >> 5;

    auto load_stage = [&](int st, int k0) {
        __half* as = As + st * A_STAGE;
        __half* bs = Bs + st * B_STAGE;
#pragma unroll
        for (int i = 0; i < 2; i++) {
            int r = ar0 + i * 64;
            cp_async16(as + r * AST + af8 * 8,
                       A + (size_t)(bm + r) * K + k0 + af8 * 8);
        }
#pragma unroll
        for (int i = 0; i < 4; i++) {
            int r = br0 + i * 8;
            cp_async16(bs + r * BST + bf8 * 8,
                       B + (size_t)(k0 + r) * N + bn + bf8 * 8);
        }
        cp_commit();
    };

    float acc[4][8][4];
#pragma unroll
    for (int mf = 0; mf < 4; mf++)
#pragma unroll
        for (int nf = 0; nf < 8; nf++)
#pragma unroll
            for (int i = 0; i < 4; i++) acc[mf][nf][i] = 0.0f;

    const int kTiles = K / BK;
    load_stage(0, 0);
    load_stage(1, BK);
    load_stage(2, 2 * BK);

    const int a_row = warpM * 64 + (lane & 15);
    const int a_k8  = (lane >> 4) * 8;
    const int b_row = (lane & 7) | (((lane >> 3) & 1) << 3);
    const int b_col = warpN * 64 + ((lane >> 4) & 1) * 8;   // + q*16

    for (int kt = 0; kt < kTiles; ++kt) {
        if (kt + 3 < kTiles) {
            load_stage((kt + 3) % STAGES, (kt + 3) * BK);
            asm volatile("cp.async.wait_group 3;\n");
        } else {
            asm volatile("cp.async.wait_group 0;\n");
        }
        __syncthreads();

        const int cur = kt % STAGES;
        const uint32_t as_base = As_u + (uint32_t)(cur * A_STAGE) * 2;
        const uint32_t bs_base = Bs_u + (uint32_t)(cur * B_STAGE) * 2;

#pragma unroll
        for (int kk = 0; kk < BK; kk += 16) {
            uint32_t a[4][4];
            uint32_t b[4][4];   // [q][4]: nf=2q -> b[q]+0, nf=2q+1 -> b[q]+2
#pragma unroll
            for (int mf = 0; mf < 4; mf++) {
                uint32_t addr = as_base +
                    ((uint32_t)(a_row + mf * 16) * AST + kk + a_k8) * 2;
                ldmA(a[mf], addr);
            }
#pragma unroll
            for (int q = 0; q < 4; q++) {
                uint32_t addr = bs_base +
                    ((uint32_t)(kk + b_row) * BST + b_col + q * 16) * 2;
                ldmB4(b[q], addr);
            }
#pragma unroll
            for (int mf = 0; mf < 4; mf++)
#pragma unroll
                for (int nf = 0; nf < 8; nf++)
                    mma_f16(acc[mf][nf], a[mf], &b[nf >> 1][(nf & 1) * 2]);
        }
        __syncthreads();
    }

#pragma unroll
    for (int mf = 0; mf < 4; mf++) {
        int r0 = bm + warpM * 64 + mf * 16 + (lane >> 2);
#pragma unroll
        for (int nf = 0; nf < 8; nf++) {
            int c0 = bn + warpN * 64 + nf * 8 + (lane & 3) * 2;
            *reinterpret_cast<float2*>(C + (size_t)r0 * N + c0) =
                make_float2(acc[mf][nf][0], acc[mf][nf][1]);
            *reinterpret_cast<float2*>(C + (size_t)(r0 + 8) * N + c0) =
                make_float2(acc[mf][nf][2], acc[mf][nf][3]);
        }
    }
}

// ---------------------------------------------------------------------------
// Launch
// ---------------------------------------------------------------------------
extern "C" void kernel_launch(void* const* d_in, const int* in_sizes, int n_in,
                              void* d_out, int out_size) {
    const float* x  = (const float*)d_in[0];
    const int*   gq = (const int*)d_in[1];
    const int*   gz = (const int*)d_in[2];
    const float* gs = (const float*)d_in[3];
    const int*   uq = (const int*)d_in[4];
    const int*   uz = (const int*)d_in[5];
    const float* us = (const float*)d_in[6];
    const int*   dq = (const int*)d_in[7];
    const int*   dz = (const int*)d_in[8];
    const float* ds = (const float*)d_in[9];
    float* out = (float*)d_out;

    __half *wg, *wu, *wd, *xh, *hh;
    cudaGetSymbolAddress((void**)&wg, g_wg);
    cudaGetSymbolAddress((void**)&wu, g_wu);
    cudaGetSymbolAddress((void**)&wd, g_wd);
    cudaGetSymbolAddress((void**)&xh, g_xh);
    cudaGetSymbolAddress((void**)&hh, g_h);

    cudaFuncSetAttribute(fused_gateup_kernel,
                         cudaFuncAttributeMaxDynamicSharedMemorySize, (int)FSMEM_BYTES);
    cudaFuncSetAttribute(gemm_f16_kernel,
                         cudaFuncAttributeMaxDynamicSharedMemorySize, (int)SMEM_BYTES);

    // 1) dequant all weights to fp16, [K, N] layout
    dequant_kernel<<<dim3(INTER / 256, HIDDEN / 8), 256>>>(gq, gz, gs, wg, HIDDEN, INTER);
    dequant_kernel<<<dim3(INTER / 256, HIDDEN / 8), 256>>>(uq, uz, us, wu, HIDDEN, INTER);
    dequant_kernel<<<dim3(HIDDEN / 256, INTER / 8), 256>>>(dq, dz, ds, wd, INTER, HIDDEN);

    // 2) x to fp16
    x_to_half_kernel<<<(TOKENS * HIDDEN / 8 + 255) / 256, 256>>>(x, xh, TOKENS * HIDDEN / 8);

    // 3) fused gate+up -> h (fp16)
    fused_gateup_kernel<<<dim3(INTER / FBN, TOKENS / FBM), 256, FSMEM_BYTES>>>(
        xh, wg, wu, hh, TOKENS, INTER, HIDDEN);

    // 4) down projection -> out (fp32)
    gemm_f16_kernel<<<dim3(HIDDEN / BN, TOKENS / BM), 256, SMEM_BYTES>>>(
        hh, wd, out, TOKENS, HIDDEN, INTER);
}